// round 7
// baseline (speedup 1.0000x reference)
#include <cuda_runtime.h>
#include <cuda_bf16.h>
#include <cuda_fp16.h>

// KAN layer: y[b,o] = sum_f lerp(coeff[f, i-1, o], coeff[f, i, o], t) + bias[o]
// B=4096, F=128, G=64, OUT=64.  i = clip(ceil((x+3)*10.5), 1, 63); t = (x+3)*10.5-(i-1)
//
// R5/R6: fp16 coeff tile in smem (fixed compile: use __half2 casts, no fake intrinsics).
//  - FC=16 features fit the same 128 KB -> NCHUNK 16->8 -> scratch halves (8.4 MB)
//  - a coeff row is now 128 B = ONE crossbar phase -> gather floor 7.2us -> 3.6us
//  - accumulation + partials stay fp32 (only coeff storage rounded: ~3e-4 rel)

#define F_DIM   128
#define G_SIZE  64
#define OUT_N   64
#define FC      16
#define NCHUNK  (F_DIM / FC)      // 8
#define NB_S    18                // sample-phases per chunk -> grid 144
#define THREADS 1024
#define B_TOTAL 4096
#define MAX_S   228               // ceil(4096/18)

#define TILE_HALVES (FC * G_SIZE * OUT_N)               // 65536 halves = 128 KB
#define SIDX_ELEMS  (MAX_S * FC)                        // 3648 float2
#define SMEM_BYTES  (TILE_HALVES * 2 + SIDX_ELEMS * 8)  // 160256 B

__device__ float g_partial[NCHUNK * B_TOTAL * OUT_N];   // 8.4 MB scratch

struct __align__(16) Half8 { __half2 a, b, c, d; };     // 8 halves = 16 B

__global__ __launch_bounds__(THREADS, 1)
void kan_h16_kernel(const float* __restrict__ x,
                    const float* __restrict__ coeff)
{
    extern __shared__ __align__(16) char smem_raw[];
    __half* tile = reinterpret_cast<__half*>(smem_raw);                 // [FC][G][OUT] fp16
    float2* sidx = reinterpret_cast<float2*>(smem_raw + TILE_HALVES*2); // [nS][FC]

    const int tid = threadIdx.x;
    const int c   = blockIdx.x & (NCHUNK - 1);   // chunk 0..7
    const int sb  = blockIdx.x >> 3;             // sample-phase 0..17
    const int nS  = (B_TOTAL - sb + NB_S - 1) / NB_S;   // 228 or 227

    // ---- Stage coeff chunk, fp32 -> fp16: 65536 floats, 8/thread/iter ----
    {
        const float4* src = reinterpret_cast<const float4*>(coeff + c * TILE_HALVES);
        Half8* dst = reinterpret_cast<Half8*>(tile);
        #pragma unroll
        for (int it = 0; it < TILE_HALVES / 8 / THREADS; ++it) {
            const int j = tid + it * THREADS;          // octet index
            const float4 a = src[2 * j];
            const float4 b = src[2 * j + 1];
            Half8 h;
            h.a = __float22half2_rn(make_float2(a.x, a.y));
            h.b = __float22half2_rn(make_float2(a.z, a.w));
            h.c = __float22half2_rn(make_float2(b.x, b.y));
            h.d = __float22half2_rn(make_float2(b.z, b.w));
            dst[j] = h;
        }
    }

    // ---- Index phase: all (sample, feature) pairs once ----
    for (int p = tid; p < nS * FC; p += THREADS) {
        const int sl = p >> 4;            // local sample
        const int ff = p & (FC - 1);
        const int b  = sb + sl * NB_S;
        const float xv = x[b * F_DIM + c * FC + ff];
        const float u  = (xv + 3.0f) * 10.5f;
        int i = (int)ceilf(u);
        i = max(1, min(i, G_SIZE - 1));
        const float t = u - (float)(i - 1);
        const int off = (ff * G_SIZE + (i - 1)) * OUT_N;   // half-element offset
        sidx[p] = make_float2(__int_as_float(off), t);
    }
    __syncthreads();   // the only barrier

    // ---- Gather: warp = 2 samples x 16 lanes; lane owns 4 outputs (8 B/row) ----
    const int lane16 = tid & 15;
    const int o4h    = lane16 << 2;                        // half offset
    const int my_s   = ((tid >> 5) << 1) + ((tid >> 4) & 1);

    const __half* cb = tile + o4h;

    for (int s = my_s; s < nS; s += 64) {
        const float2* sp = sidx + s * FC;
        float4 acc = make_float4(0.f, 0.f, 0.f, 0.f);

        #pragma unroll
        for (int f = 0; f < FC; ++f) {
            const float2 bt = sp[f];                       // broadcast over 16 lanes
            const __half* p = cb + __float_as_int(bt.x);
            const __half2 r0a = *reinterpret_cast<const __half2*>(p);           // c0[0:2]
            const __half2 r0b = *reinterpret_cast<const __half2*>(p + 2);       // c0[2:4]
            const __half2 r1a = *reinterpret_cast<const __half2*>(p + OUT_N);   // c1[0:2]
            const __half2 r1b = *reinterpret_cast<const __half2*>(p + OUT_N + 2);
            const float2 a0 = __half22float2(r0a);
            const float2 a1 = __half22float2(r0b);
            const float2 b0 = __half22float2(r1a);
            const float2 b1 = __half22float2(r1b);
            const float t = bt.y;
            acc.x += a0.x + t * (b0.x - a0.x);
            acc.y += a0.y + t * (b0.y - a0.y);
            acc.z += a1.x + t * (b1.x - a1.x);
            acc.w += a1.y + t * (b1.y - a1.y);
        }

        const int b = sb + s * NB_S;
        *reinterpret_cast<float4*>(
            g_partial + ((c * B_TOTAL) + b) * OUT_N + o4h) = acc;
    }
}

// y[e] = bias[e&63] + sum_c partial[c*B*OUT + e]
__global__ __launch_bounds__(256)
void kan_reduce_kernel(const float* __restrict__ bias,
                       float* __restrict__ y)
{
    const int e = blockIdx.x * 256 + threadIdx.x;   // 0..262143
    const int o = e & (OUT_N - 1);

    float acc = __ldg(bias + o);
    const float* p = g_partial + e;

    #pragma unroll
    for (int c = 0; c < NCHUNK; ++c)
        acc += p[c * (B_TOTAL * OUT_N)];

    y[e] = acc;
}

extern "C" void kernel_launch(void* const* d_in, const int* in_sizes, int n_in,
                              void* d_out, int out_size)
{
    const float* x     = (const float*)d_in[0];   // [4096, 128]
    const float* coeff = (const float*)d_in[1];   // [128, 64, 64]
    const float* bias  = (const float*)d_in[2];   // [64]
    float* y           = (float*)d_out;           // [4096, 64]

    static int configured = 0;
    if (!configured) {
        cudaFuncSetAttribute(kan_h16_kernel,
                             cudaFuncAttributeMaxDynamicSharedMemorySize, SMEM_BYTES);
        configured = 1;
    }

    kan_h16_kernel<<<NCHUNK * NB_S, THREADS, SMEM_BYTES>>>(x, coeff);
    kan_reduce_kernel<<<B_TOTAL * OUT_N / 256, 256>>>(bias, y);
}

// round 8
// speedup vs baseline: 1.0016x; 1.0016x over previous
#include <cuda_runtime.h>
#include <cuda_bf16.h>
#include <cuda_fp16.h>

// KAN layer: y[b,o] = sum_f lerp(coeff[f, i-1, o], coeff[f, i, o], t) + bias[o]
// B=4096, F=128, G=64, OUT=64.  i = clip(ceil((x+3)*10.5), 1, 63); t = (x+3)*10.5-(i-1)
//
// R7: single-pass fp16 L1/L2 gather, NO scratch round-trip.
//  - coeff pre-converted to fp16 (1 MB __device__): one row = 64 halves = 128 B
//    = ONE L1 line.
//  - warp = 1 sample, lane owns outputs {2l,2l+1}: each row fetch is one LDG.32
//    touching exactly one line -> cross-LDG 1.0 cyc/wf rate (no 2.07 replay tax).
//    Gather floor ~3.6us.
//  - warp accumulates all 128 features in registers: reduce kernel (5.6us tax)
//    is GONE. Lerp in fp32 after cvt (keeps rel_err ~2e-4).

#define F_DIM   128
#define G_SIZE  64
#define OUT_N   64
#define SPB     8
#define THREADS 256
#define B_TOTAL 4096

__device__ __half g_ch[F_DIM * G_SIZE * OUT_N];   // 1 MB fp16 coeff

struct __align__(8) H4 { __half2 a, b; };

// coeff fp32 -> fp16, 131072 float4s
__global__ __launch_bounds__(256)
void kan_convert_kernel(const float* __restrict__ coeff)
{
    const int j = blockIdx.x * 256 + threadIdx.x;   // 0..131071
    const float4 v = reinterpret_cast<const float4*>(coeff)[j];
    H4 h;
    h.a = __float22half2_rn(make_float2(v.x, v.y));
    h.b = __float22half2_rn(make_float2(v.z, v.w));
    reinterpret_cast<H4*>(g_ch)[j] = h;
}

__global__ __launch_bounds__(THREADS)
void kan_main_kernel(const float* __restrict__ x,
                     const float* __restrict__ bias,
                     float* __restrict__ y)
{
    __shared__ float2 sidx[SPB * F_DIM];   // 8 KB: (.x = half-elem offset bits, .y = t)

    const int tid  = threadIdx.x;
    const int row0 = blockIdx.x * SPB;

    // ---- Phase 1: all (sample, feature) -> (offset, t), once. ----
    // Thread handles 4 consecutive features of one sample (coalesced float4 x).
    {
        const int s  = tid >> 5;          // 0..7
        const int f0 = (tid & 31) << 2;   // 0..124
        const float4 xv = *reinterpret_cast<const float4*>(x + (row0 + s) * F_DIM + f0);
        const float xs[4] = {xv.x, xv.y, xv.z, xv.w};
        #pragma unroll
        for (int k = 0; k < 4; ++k) {
            const float u = (xs[k] + 3.0f) * 10.5f;
            int i = (int)ceilf(u);
            i = max(1, min(i, G_SIZE - 1));
            const float t = u - (float)(i - 1);
            const int off = ((f0 + k) * G_SIZE + (i - 1)) * OUT_N;   // in halves
            sidx[s * F_DIM + f0 + k] = make_float2(__int_as_float(off), t);
        }
    }
    __syncthreads();

    // ---- Phase 2: warp = sample; lane owns outputs {2l, 2l+1}. ----
    const int w    = tid >> 5;
    const int lane = tid & 31;

    float2 acc = reinterpret_cast<const float2*>(bias)[lane];
    const float2* sp = sidx + w * F_DIM;

    #pragma unroll 4
    for (int f = 0; f < F_DIM; ++f) {
        const float2 bt = sp[f];                         // LDS.64 broadcast
        const __half2* p =
            reinterpret_cast<const __half2*>(g_ch + __float_as_int(bt.x)) + lane;
        const __half2 h0 = p[0];                         // row i-1: one 128B line
        const __half2 h1 = p[OUT_N / 2];                 // row i:   one 128B line
        const float2 a = __half22float2(h0);
        const float2 b = __half22float2(h1);
        const float t = bt.y;
        acc.x += a.x + t * (b.x - a.x);
        acc.y += a.y + t * (b.y - a.y);
    }

    reinterpret_cast<float2*>(y + (row0 + w) * OUT_N)[lane] = acc;   // coalesced
}

extern "C" void kernel_launch(void* const* d_in, const int* in_sizes, int n_in,
                              void* d_out, int out_size)
{
    const float* x     = (const float*)d_in[0];   // [4096, 128]
    const float* coeff = (const float*)d_in[1];   // [128, 64, 64]
    const float* bias  = (const float*)d_in[2];   // [64]
    float* y           = (float*)d_out;           // [4096, 64]

    kan_convert_kernel<<<F_DIM * G_SIZE * OUT_N / 4 / 256, 256>>>(coeff);
    kan_main_kernel<<<B_TOTAL / SPB, THREADS>>>(x, bias, y);
}

// round 9
// speedup vs baseline: 1.1978x; 1.1959x over previous
#include <cuda_runtime.h>
#include <cuda_bf16.h>
#include <cuda_fp16.h>
#include <cstring>

// KAN layer: y[b,o] = sum_f lerp(coeff[f, i-1, o], coeff[f, i, o], t) + bias[o]
// B=4096, F=128, G=64, OUT=64.  i = clip(ceil((x+3)*10.5), 1, 63); t = (x+3)*10.5-(i-1)
//
// R8: single-pass fp16 gather, now issue/latency-optimized:
//  - 2 warps per sample (64 features each) -> 8192 warps (~50/SM), smem pair-add
//  - 4-feature load batching -> 8 single-line LDG.32 in flight per warp
//  - fp16 lerp (HSUB2+HFMA2) + fp32 accumulate; t pre-packed as half2 in sidx
//    (per-feature warp-instrs 13 -> ~9)

#define F_DIM   128
#define G_SIZE  64
#define OUT_N   64
#define SPB     4                 // samples per block
#define THREADS 256               // 8 warps = 4 samples x 2 feature-halves
#define B_TOTAL 4096
#define FH      64                // features per warp

__device__ __half g_ch[F_DIM * G_SIZE * OUT_N];   // 1 MB fp16 coeff

struct __align__(8) H4 { __half2 a, b; };

// coeff fp32 -> fp16, 131072 float4s
__global__ __launch_bounds__(256)
void kan_convert_kernel(const float* __restrict__ coeff)
{
    const int j = blockIdx.x * 256 + threadIdx.x;
    const float4 v = reinterpret_cast<const float4*>(coeff)[j];
    H4 h;
    h.a = __float22half2_rn(make_float2(v.x, v.y));
    h.b = __float22half2_rn(make_float2(v.z, v.w));
    reinterpret_cast<H4*>(g_ch)[j] = h;
}

__global__ __launch_bounds__(THREADS, 6)
void kan_main_kernel(const float* __restrict__ x,
                     const float* __restrict__ bias,
                     float* __restrict__ y)
{
    __shared__ uint2  sidx[SPB * F_DIM];    // 4 KB: (.x = half-elem offset, .y = half2(t,t) bits)
    __shared__ float2 part[SPB][32];        // 1 KB: odd-warp partials

    const int tid  = threadIdx.x;
    const int row0 = blockIdx.x * SPB;

    // ---- Phase 1: all (sample, feature) -> (offset, t-packed), once ----
    #pragma unroll
    for (int k = 0; k < (SPB * F_DIM) / THREADS; ++k) {
        const int p = tid + k * THREADS;
        const int s = p >> 7;              // 0..3
        const int f = p & (F_DIM - 1);     // coalesced over f
        const float xv = x[(row0 + s) * F_DIM + f];
        const float u  = (xv + 3.0f) * 10.5f;
        int i = (int)ceilf(u);
        i = max(1, min(i, G_SIZE - 1));
        const float t = u - (float)(i - 1);
        const __half2 th = __float2half2_rn(t);
        unsigned tb; memcpy(&tb, &th, 4);
        sidx[p] = make_uint2((unsigned)((f * G_SIZE + (i - 1)) * OUT_N), tb);
    }
    __syncthreads();

    // ---- Phase 2: warp = (sample, feature-half); lane owns outputs {2l,2l+1} ----
    const int w    = tid >> 5;
    const int lane = tid & 31;
    const int s    = w >> 1;               // 0..3
    const int h    = w & 1;                // feature half

    const uint2* sp = sidx + s * F_DIM + h * FH;

    float2 acc = make_float2(0.f, 0.f);

    for (int f0 = 0; f0 < FH; f0 += 4) {
        // stage 4 features: 8 independent single-line LDG.32
        __half2 c0[4], c1[4], t2[4];
        #pragma unroll
        for (int j = 0; j < 4; ++j) {
            const uint2 e = sp[f0 + j];
            memcpy(&t2[j], &e.y, 4);
            const __half2* p = reinterpret_cast<const __half2*>(g_ch + e.x) + lane;
            c0[j] = p[0];                  // row i-1: one 128B line for the warp
            c1[j] = p[OUT_N / 2];          // row i
        }
        #pragma unroll
        for (int j = 0; j < 4; ++j) {
            const __half2 d = __hsub2(c1[j], c0[j]);
            const __half2 r = __hfma2(t2[j], d, c0[j]);    // fp16 lerp
            const float2 rf = __half22float2(r);
            acc.x += rf.x;                                  // fp32 accumulate
            acc.y += rf.y;
        }
    }

    // ---- Phase 3: pair reduction + bias + store ----
    if (h == 1) {
        part[s][lane] = acc;
    }
    __syncthreads();
    if (h == 0) {
        const float2 pr = part[s][lane];
        const float2 bv = reinterpret_cast<const float2*>(bias)[lane];
        acc.x += pr.x + bv.x;
        acc.y += pr.y + bv.y;
        reinterpret_cast<float2*>(y + (row0 + s) * OUT_N)[lane] = acc;  // coalesced
    }
}

extern "C" void kernel_launch(void* const* d_in, const int* in_sizes, int n_in,
                              void* d_out, int out_size)
{
    const float* x     = (const float*)d_in[0];   // [4096, 128]
    const float* coeff = (const float*)d_in[1];   // [128, 64, 64]
    const float* bias  = (const float*)d_in[2];   // [64]
    float* y           = (float*)d_out;           // [4096, 64]

    kan_convert_kernel<<<F_DIM * G_SIZE * OUT_N / 4 / 256, 256>>>(coeff);
    kan_main_kernel<<<B_TOTAL / SPB, THREADS>>>(x, bias, y);
}